// round 14
// baseline (speedup 1.0000x reference)
#include <cuda_runtime.h>
#include <math.h>

// Input: (2, 40, 40, 40) fp32. One block per (batch, z-plane).
//
// Final champion (v11 family). Structure:
//   - Phase A: all 512 threads stage 4-bit occupancy nibbles of the 3-plane
//     target window into shared; 120 threads assemble 40-bit row words.
//   - Phase B: each thread owns one float4 of input; pred voxels (>2.0) do a
//     row-wise 1-NN against the OR-folded 3x3 row neighborhood; guaranteed-
//     correct expanding-ring fallback reads target from global (P ~ 2^-33).
//   - Epilogue: warp shuffle-reduce into a packed u64; ONE global atomicAdd
//     per warp (arrivals | count | fixed-point sum) -> order-independent,
//     bit-deterministic; last warp computes the mean and writes d_out.
// Wall time is pinned at the launch+latency floor (8.67 us); three distinct
// structures tie here and both attempted "improvements" regressed.
#define NVOX   64000
#define GRID   80          // 2 batches * 40 planes
#define TPB    512
#define F4PB   400         // 1600 voxels per plane / 4
#define SROWN  210         // padded row mask: 5 plane-slots * 42 y-slots
#define NBROWS 120         // max rows in 3-plane window
#define SBYTEW 16          // padded bytes per staging row
#define NWARPT (GRID * (TPB / 32))   // 1280 warp arrivals

typedef unsigned long long u64;

// [63:53] warp arrivals, [52:40] pred count, [39:0] sum * 2^20.
__device__ u64 g_acc = 0ULL;   // reset by last warp (graph-replay safe)

// min over set bits of (bitpos - x)^2 ; ~(1<<20) sentinel if empty
__device__ __forceinline__ int row_d2(u64 w, int x) {
    u64 low  = w & ((2ULL << x) - 1ULL);   // bits 0..x
    u64 high = (w >> x) >> 1;              // bits x+1..
    int dl = low  ? (x - (63 - __clzll((long long)low))) : (1 << 10);
    int dh = high ? __ffsll((long long)high)             : (1 << 10);
    int d  = min(dl, dh);
    return d * d;
}

// Pack 8 nibble-valued bytes (u64) into 32 bits.
__device__ __forceinline__ unsigned pack8(u64 B) {
    u64 x = (B | (B >> 4))  & 0x00FF00FF00FF00FFULL;
    x     = (x | (x >> 8))  & 0x0000FFFF0000FFFFULL;
    x     = (x | (x >> 16));
    return (unsigned)x;
}

// Fallback only (P ~ 2^-33 per pred): scan a target row straight from global.
__device__ __noinline__ int global_row_d2(const float* __restrict__ t,
                                          int zz, int yy, int x) {
    const float* r = t + zz * 1600 + yy * 40;
    int best = 1 << 20;
    for (int xx = 0; xx < 40; ++xx)
        if (r[xx] > 0.0f) { int dx = xx - x; best = min(best, dx * dx); }
    return best;
}

__global__ __launch_bounds__(TPB, 1)
void mdist_final(const float* __restrict__ inp, const float* __restrict__ tgt,
                 float* __restrict__ out, int out_size) {
    __shared__ u64           srow[SROWN];
    __shared__ unsigned char sbyte[NBROWS * SBYTEW];   // nibble staging

    const int tid   = threadIdx.x;
    const int bid   = blockIdx.x;
    const int lane  = tid & 31;
    const int batch = bid >= 40;       // 40 planes per batch
    const int z     = bid - batch * 40;

    const float* t = tgt + batch * NVOX;

    // ---- Window: plane z with +-1 halo (<= 3 planes) ----
    const int zlo     = max(z - 1, 0);
    const int zhi     = min(z + 1, 39);
    const int nplanes = zhi - zlo + 1;
    const int nf4     = nplanes * F4PB;    // <= 1200
    const int nrow    = nplanes * 40;      // <= 120

    // ---- Issue all loads up-front: input f4 + <=3 target f4 ----
    float4 q = make_float4(0.f, 0.f, 0.f, 0.f);
    if (tid < F4PB)
        q = ((const float4*)inp)[batch * (NVOX / 4) + z * F4PB + tid];

    const float4* tw = (const float4*)(t + zlo * 1600);
    float4 tv[3];
#pragma unroll
    for (int s = 0; s < 3; ++s) {
        const int j = tid + s * TPB;
        if (j < nf4) tv[s] = tw[j];
    }

    // ---- Zero ONLY the pad slots of srow (disjoint from assembly writes,
    //      so no sync needed between this and the assembly phase) ----
    if (tid < SROWN) {
        const int pl = tid / 42, yy = tid - pl * 42;
        const bool interior = (pl >= 1) & (pl <= nplanes) &
                              (yy >= 1) & (yy <= 40);
        if (!interior) srow[tid] = 0ULL;
    }

    // ---- Nibble staging: one byte per float4 quad (no staging zero needed:
    //      assembly reads only bytes 0..9, all written for rows < nrow) ----
#pragma unroll
    for (int s = 0; s < 3; ++s) {
        const int j = tid + s * TPB;
        if (j < nf4) {
            const unsigned bits = (tv[s].x > 0.0f)        |
                                  ((tv[s].y > 0.0f) << 1) |
                                  ((tv[s].z > 0.0f) << 2) |
                                  ((tv[s].w > 0.0f) << 3);
            const int row = j / 10;
            sbyte[row * SBYTEW + (j - row * 10)] = (unsigned char)bits;
        }
    }
    __syncthreads();

    // ---- Assemble row words (one thread per row, no ballots/atomics) ----
    if (tid < nrow) {
        const u64 lo = *(const u64*)(sbyte + tid * SBYTEW);
        const unsigned hi2 = *(const unsigned short*)(sbyte + tid * SBYTEW + 8);
        const unsigned hi = (hi2 & 0xFu) | ((hi2 >> 4) & 0xF0u);  // n8|n9<<4
        const u64 w = (u64)pack8(lo) | ((u64)hi << 32);
        const int pl = tid / 40, yy = tid - pl * 40;
        srow[(pl + 1) * 42 + yy + 1] = w;
    }
    __syncthreads();

    // ---- Pred scan: z constant per block; y = tid/10, x0 = (tid%10)*4 ----
    u64 lacc = 0ULL;
    if (tid < F4PB) {
        const float qa[4] = {q.x, q.y, q.z, q.w};
        const bool anyp = (qa[0] > 2.0f) | (qa[1] > 2.0f) |
                          (qa[2] > 2.0f) | (qa[3] > 2.0f);
        if (anyp) {
            const int y  = tid / 10;
            const int x0 = (tid - y * 10) * 4;

            const u64* base = srow + (z - zlo + 1) * 42 + (y + 1);
            const u64 c0 = base[0];
            const u64 r1 = base[-1]  | base[1]  | base[-42] | base[42];
            const u64 r2 = base[-43] | base[-41] | base[41] | base[43];

#pragma unroll
            for (int c = 0; c < 4; ++c) {
                if (qa[c] > 2.0f) {
                    const int x = x0 + c;
                    int best = min(min(row_d2(c0, x),
                                       row_d2(r1, x) + 1),
                                       row_d2(r2, x) + 2);
                    // Rare fallback: expanding rings of whole rows (global).
                    // After ring r every unscanned row has dz^2+dy^2>=(r+1)^2.
                    if (best > 4) {
                        for (int r = 2; r <= 39; ++r) {
                            if (best <= r * r) break;
                            for (int dz = -r; dz <= r; ++dz) {
                                const int zz = z + dz;
                                if ((unsigned)zz >= 40u) continue;
                                const int step = (abs(dz) == r) ? 1 : 2 * r;
                                for (int dy = -r; dy <= r; dy += step) {
                                    const int yy = y + dy;
                                    if ((unsigned)yy >= 40u) continue;
                                    best = min(best, dz * dz + dy * dy +
                                                     global_row_d2(t, zz, yy, x));
                                }
                            }
                        }
                    }
                    // count in [52:40]; sum*2^20 in [39:0].
                    u64 add = 1ULL << 40;
                    if (best <= 4563)   // else: no true voxels -> distance 0
                        add += (u64)__float2uint_rn(sqrtf((float)best) *
                                                    1048576.0f);
                    lacc += add;
                }
            }
        }
    }

    // ---- Warp reduce, then ONE global atomic per warp (1280 total) ----
#pragma unroll
    for (int off = 16; off; off >>= 1)
        lacc += __shfl_down_sync(0xffffffffu, lacc, off);

    if (lane == 0) {
        const u64 contrib = lacc + (1ULL << 53);       // warp-arrival marker
        const u64 old = atomicAdd(&g_acc, contrib);
        if ((old >> 53) == NWARPT - 1) {               // I'm the last arrival
            const u64 tot = old + contrib;
            const int cnt = (int)((tot >> 40) & 0x1FFFULL);
            const double sum = (double)(tot & ((1ULL << 40) - 1ULL)) *
                               (1.0 / 1048576.0);
            const float val = (cnt > 0) ? (float)(sum / (double)cnt) : 0.0f;
            for (int i = 0; i < out_size; ++i) out[i] = val;
            g_acc = 0ULL;   // reset for next graph replay
        }
    }
}

extern "C" void kernel_launch(void* const* d_in, const int* in_sizes, int n_in,
                              void* d_out, int out_size) {
    const float* inp = (const float*)d_in[0];
    const float* tgt = (const float*)d_in[1];
    (void)in_sizes; (void)n_in;
    mdist_final<<<GRID, TPB>>>(inp, tgt, (float*)d_out, out_size);
}

// round 15
// speedup vs baseline: 1.0332x; 1.0332x over previous
#include <cuda_runtime.h>
#include <math.h>

// Input: (2, 40, 40, 40) fp32. One block per (batch, z-plane).
//
// Final champion (v11 family), floor-confirmed:
//   - Phase A: all 512 threads stage 4-bit occupancy nibbles of the 3-plane
//     target window into shared; 120 threads assemble 40-bit row words.
//   - Phase B: each thread owns one float4 of input; pred voxels (>2.0) do a
//     row-wise 1-NN against the OR-folded 3x3 row neighborhood; guaranteed-
//     correct expanding-ring fallback reads target from global (P ~ 2^-33).
//   - Epilogue: warp shuffle-reduce into a packed u64; ONE global atomicAdd
//     per warp (arrivals | count | fixed-point sum) -> order-independent,
//     bit-deterministic; last warp computes the mean and writes d_out.
// Wall time is launch+latency floor (8.7 +- 0.3 us run noise); identical code
// measured 8.672 and 8.96 us, bounding every remaining lever below noise.
#define NVOX   64000
#define GRID   80          // 2 batches * 40 planes
#define TPB    512
#define F4PB   400         // 1600 voxels per plane / 4
#define SROWN  210         // padded row mask: 5 plane-slots * 42 y-slots
#define NBROWS 120         // max rows in 3-plane window
#define SBYTEW 16          // padded bytes per staging row
#define NWARPT (GRID * (TPB / 32))   // 1280 warp arrivals

typedef unsigned long long u64;

// [63:53] warp arrivals, [52:40] pred count, [39:0] sum * 2^20.
__device__ u64 g_acc = 0ULL;   // reset by last warp (graph-replay safe)

// min over set bits of (bitpos - x)^2 ; ~(1<<20) sentinel if empty
__device__ __forceinline__ int row_d2(u64 w, int x) {
    u64 low  = w & ((2ULL << x) - 1ULL);   // bits 0..x
    u64 high = (w >> x) >> 1;              // bits x+1..
    int dl = low  ? (x - (63 - __clzll((long long)low))) : (1 << 10);
    int dh = high ? __ffsll((long long)high)             : (1 << 10);
    int d  = min(dl, dh);
    return d * d;
}

// Pack 8 nibble-valued bytes (u64) into 32 bits.
__device__ __forceinline__ unsigned pack8(u64 B) {
    u64 x = (B | (B >> 4))  & 0x00FF00FF00FF00FFULL;
    x     = (x | (x >> 8))  & 0x0000FFFF0000FFFFULL;
    x     = (x | (x >> 16));
    return (unsigned)x;
}

// Fallback only (P ~ 2^-33 per pred): scan a target row straight from global.
__device__ __noinline__ int global_row_d2(const float* __restrict__ t,
                                          int zz, int yy, int x) {
    const float* r = t + zz * 1600 + yy * 40;
    int best = 1 << 20;
    for (int xx = 0; xx < 40; ++xx)
        if (r[xx] > 0.0f) { int dx = xx - x; best = min(best, dx * dx); }
    return best;
}

__global__ __launch_bounds__(TPB, 1)
void mdist_final(const float* __restrict__ inp, const float* __restrict__ tgt,
                 float* __restrict__ out, int out_size) {
    __shared__ u64           srow[SROWN];
    __shared__ unsigned char sbyte[NBROWS * SBYTEW];   // nibble staging

    const int tid   = threadIdx.x;
    const int bid   = blockIdx.x;
    const int lane  = tid & 31;
    const int batch = bid >= 40;       // 40 planes per batch
    const int z     = bid - batch * 40;

    const float* t = tgt + batch * NVOX;

    // ---- Window: plane z with +-1 halo (<= 3 planes) ----
    const int zlo     = max(z - 1, 0);
    const int zhi     = min(z + 1, 39);
    const int nplanes = zhi - zlo + 1;
    const int nf4     = nplanes * F4PB;    // <= 1200
    const int nrow    = nplanes * 40;      // <= 120

    // ---- Issue all loads up-front: input f4 + <=3 target f4 ----
    float4 q = make_float4(0.f, 0.f, 0.f, 0.f);
    if (tid < F4PB)
        q = ((const float4*)inp)[batch * (NVOX / 4) + z * F4PB + tid];

    const float4* tw = (const float4*)(t + zlo * 1600);
    float4 tv[3];
#pragma unroll
    for (int s = 0; s < 3; ++s) {
        const int j = tid + s * TPB;
        if (j < nf4) tv[s] = tw[j];
    }

    // ---- Zero ONLY the pad slots of srow (disjoint from assembly writes,
    //      so no sync needed between this and the assembly phase) ----
    if (tid < SROWN) {
        const int pl = tid / 42, yy = tid - pl * 42;
        const bool interior = (pl >= 1) & (pl <= nplanes) &
                              (yy >= 1) & (yy <= 40);
        if (!interior) srow[tid] = 0ULL;
    }

    // ---- Nibble staging: one byte per float4 quad (no staging zero needed:
    //      assembly reads only bytes 0..9, all written for rows < nrow) ----
#pragma unroll
    for (int s = 0; s < 3; ++s) {
        const int j = tid + s * TPB;
        if (j < nf4) {
            const unsigned bits = (tv[s].x > 0.0f)        |
                                  ((tv[s].y > 0.0f) << 1) |
                                  ((tv[s].z > 0.0f) << 2) |
                                  ((tv[s].w > 0.0f) << 3);
            const int row = j / 10;
            sbyte[row * SBYTEW + (j - row * 10)] = (unsigned char)bits;
        }
    }
    __syncthreads();

    // ---- Assemble row words (one thread per row, no ballots/atomics) ----
    if (tid < nrow) {
        const u64 lo = *(const u64*)(sbyte + tid * SBYTEW);
        const unsigned hi2 = *(const unsigned short*)(sbyte + tid * SBYTEW + 8);
        const unsigned hi = (hi2 & 0xFu) | ((hi2 >> 4) & 0xF0u);  // n8|n9<<4
        const u64 w = (u64)pack8(lo) | ((u64)hi << 32);
        const int pl = tid / 40, yy = tid - pl * 40;
        srow[(pl + 1) * 42 + yy + 1] = w;
    }
    __syncthreads();

    // ---- Pred scan: z constant per block; y = tid/10, x0 = (tid%10)*4 ----
    u64 lacc = 0ULL;
    if (tid < F4PB) {
        const float qa[4] = {q.x, q.y, q.z, q.w};
        const bool anyp = (qa[0] > 2.0f) | (qa[1] > 2.0f) |
                          (qa[2] > 2.0f) | (qa[3] > 2.0f);
        if (anyp) {
            const int y  = tid / 10;
            const int x0 = (tid - y * 10) * 4;

            const u64* base = srow + (z - zlo + 1) * 42 + (y + 1);
            const u64 c0 = base[0];
            const u64 r1 = base[-1]  | base[1]  | base[-42] | base[42];
            const u64 r2 = base[-43] | base[-41] | base[41] | base[43];

#pragma unroll
            for (int c = 0; c < 4; ++c) {
                if (qa[c] > 2.0f) {
                    const int x = x0 + c;
                    int best = min(min(row_d2(c0, x),
                                       row_d2(r1, x) + 1),
                                       row_d2(r2, x) + 2);
                    // Rare fallback: expanding rings of whole rows (global).
                    // After ring r every unscanned row has dz^2+dy^2>=(r+1)^2.
                    if (best > 4) {
                        for (int r = 2; r <= 39; ++r) {
                            if (best <= r * r) break;
                            for (int dz = -r; dz <= r; ++dz) {
                                const int zz = z + dz;
                                if ((unsigned)zz >= 40u) continue;
                                const int step = (abs(dz) == r) ? 1 : 2 * r;
                                for (int dy = -r; dy <= r; dy += step) {
                                    const int yy = y + dy;
                                    if ((unsigned)yy >= 40u) continue;
                                    best = min(best, dz * dz + dy * dy +
                                                     global_row_d2(t, zz, yy, x));
                                }
                            }
                        }
                    }
                    // count in [52:40]; sum*2^20 in [39:0].
                    u64 add = 1ULL << 40;
                    if (best <= 4563)   // else: no true voxels -> distance 0
                        add += (u64)__float2uint_rn(sqrtf((float)best) *
                                                    1048576.0f);
                    lacc += add;
                }
            }
        }
    }

    // ---- Warp reduce, then ONE global atomic per warp (1280 total) ----
#pragma unroll
    for (int off = 16; off; off >>= 1)
        lacc += __shfl_down_sync(0xffffffffu, lacc, off);

    if (lane == 0) {
        const u64 contrib = lacc + (1ULL << 53);       // warp-arrival marker
        const u64 old = atomicAdd(&g_acc, contrib);
        if ((old >> 53) == NWARPT - 1) {               // I'm the last arrival
            const u64 tot = old + contrib;
            const int cnt = (int)((tot >> 40) & 0x1FFFULL);
            const double sum = (double)(tot & ((1ULL << 40) - 1ULL)) *
                               (1.0 / 1048576.0);
            const float val = (cnt > 0) ? (float)(sum / (double)cnt) : 0.0f;
            out[0] = val;                               // scalar fast path
            for (int i = 1; i < out_size; ++i) out[i] = val;
            g_acc = 0ULL;   // reset for next graph replay
        }
    }
}

extern "C" void kernel_launch(void* const* d_in, const int* in_sizes, int n_in,
                              void* d_out, int out_size) {
    const float* inp = (const float*)d_in[0];
    const float* tgt = (const float*)d_in[1];
    (void)in_sizes; (void)n_in;
    mdist_final<<<GRID, TPB>>>(inp, tgt, (float*)d_out, out_size);
}